// round 1
// baseline (speedup 1.0000x reference)
#include <cuda_runtime.h>

// Problem constants (fixed shapes per reference)
#define BB 8
#define TT 32768
#define FIN 64
#define HID 32
#define FF 64
#define NS 64
#define LCH 128                 // chunk length
#define NCHUNK (TT / LCH)       // 256 chunks per batch
#define TOTCHUNK (BB * NCHUNK)  // 2048

// Derived parameters + scratch (device globals: no allocation allowed)
__device__ float g_A[NS];       // decay per state
__device__ float g_AL[NS];      // A^L per state
__device__ float g_w[NS];       // C*P per state
__device__ float g_wU[HID];     // W2 @ Wu
__device__ float g_wD[HID];     // W2 @ D
__device__ float g_cU;          // b2 @ Wu
__device__ float g_cDy;         // b2 @ D + b_y
__device__ float g_u[BB * TT];          // scalar drive per timestep (1 MB)
__device__ float g_end[TOTCHUNK * NS];  // per-chunk local end states
__device__ float g_carry[TOTCHUNK * NS];// carry-in state per chunk

// ---------------------------------------------------------------------------
// K0: derive folded parameters. One block, 64 threads.
// ---------------------------------------------------------------------------
__global__ void k0_params(const float* __restrict__ W2, const float* __restrict__ b2,
                          const float* __restrict__ Lraw, const float* __restrict__ P,
                          const float* __restrict__ Wu, const float* __restrict__ Cv,
                          const float* __restrict__ Dv, const float* __restrict__ b_y) {
    int tid = threadIdx.x;
    if (tid < NS) {
        float lr = Lraw[tid];
        float sp = (lr > 20.f) ? lr : log1pf(expf(lr));   // softplus
        g_A[tid]  = expf(-sp);
        g_AL[tid] = expf(-sp * (float)LCH);               // A^L exactly
        g_w[tid]  = Cv[tid] * P[tid];
    }
    if (tid < HID) {
        float su = 0.f, sd = 0.f;
        for (int f = 0; f < FF; f++) {
            float w2 = W2[tid * FF + f];
            su = fmaf(w2, Wu[f], su);
            sd = fmaf(w2, Dv[f], sd);
        }
        g_wU[tid] = su;
        g_wD[tid] = sd;
    }
    if (tid == 0) {
        float cu = 0.f, cd = 0.f;
        for (int f = 0; f < FF; f++) {
            cu = fmaf(b2[f], Wu[f], cu);
            cd = fmaf(b2[f], Dv[f], cd);
        }
        g_cU  = cu;
        g_cDy = cd + b_y[0];
    }
}

// ---------------------------------------------------------------------------
// K1: per-timestep MLP -> u[t], feedthrough d[t]; plus per-chunk end state.
// One block = one chunk of LCH timesteps, one thread per timestep.
// ---------------------------------------------------------------------------
__global__ void __launch_bounds__(LCH) k1_mlp(const float* __restrict__ x,
                                              const float* __restrict__ W1,
                                              const float* __restrict__ b1,
                                              float* __restrict__ yout) {
    __shared__ float xs[LCH][FIN + 1];     // stride 65: conflict-free row reads
    __shared__ float W1s[FIN * HID];       // 2048 floats
    __shared__ float us[LCH];
    __shared__ float wUs[HID], wDs[HID], b1s[HID];
    __shared__ float cUs, cDys;

    const int tid = threadIdx.x;
    const int chunk = blockIdx.x;
    const long t0 = (long)chunk * LCH;     // global timestep index base (b*T + c*L)

    // Stage W1 and small vectors
    for (int e = tid; e < FIN * HID; e += LCH) W1s[e] = W1[e];
    if (tid < HID) { wUs[tid] = g_wU[tid]; wDs[tid] = g_wD[tid]; b1s[tid] = b1[tid]; }
    if (tid == 0) { cUs = g_cU; cDys = g_cDy; }

    // Stage x tile, coalesced float4 loads
    const float4* xg = (const float4*)(x + t0 * FIN);
    #pragma unroll
    for (int e = tid; e < LCH * (FIN / 4); e += LCH) {
        float4 v = xg[e];
        int row = e >> 4;            // FIN/4 == 16 vec4 per row
        int col = (e & 15) << 2;
        xs[row][col + 0] = v.x; xs[row][col + 1] = v.y;
        xs[row][col + 2] = v.z; xs[row][col + 3] = v.w;
    }
    __syncthreads();

    // h = relu(x @ W1 + b1); u = h@wU + cU; d = h@wD + cDy
    float h[HID];
    #pragma unroll
    for (int j = 0; j < HID; j++) h[j] = b1s[j];

    const float* xr = xs[tid];
    #pragma unroll 4
    for (int i = 0; i < FIN; i++) {
        float xv = xr[i];
        const float* wrow = &W1s[i * HID];
        #pragma unroll
        for (int j = 0; j < HID; j++) h[j] = fmaf(xv, wrow[j], h[j]);
    }
    float u = cUs, d = cDys;
    #pragma unroll
    for (int j = 0; j < HID; j++) {
        float hj = fmaxf(h[j], 0.f);
        u = fmaf(hj, wUs[j], u);
        d = fmaf(hj, wDs[j], d);
    }
    us[tid] = u;
    g_u[t0 + tid] = u;
    yout[t0 + tid] = d;                  // feedthrough part of y (finished in K3)
    __syncthreads();

    // Warp 0: local end-state of this chunk (zero initial condition)
    if (tid < 32) {
        float a0 = g_A[tid], a1 = g_A[tid + 32];
        float r0 = 0.f, r1 = 0.f;
        #pragma unroll 8
        for (int t = 0; t < LCH; t++) {
            float uv = us[t];
            r0 = fmaf(a0, r0, uv);
            r1 = fmaf(a1, r1, uv);
        }
        g_end[chunk * NS + tid]      = r0;
        g_end[chunk * NS + tid + 32] = r1;
    }
}

// ---------------------------------------------------------------------------
// K2: scan carries across chunks, per batch. One block per batch, 64 threads
// (thread = state). Loads batched 8-wide so the FMA chain isn't latency-bound.
// ---------------------------------------------------------------------------
__global__ void __launch_bounds__(NS) k2_carry() {
    const int b = blockIdx.x;
    const int n = threadIdx.x;
    const float al = g_AL[n];
    float carry = 0.f;
    const float* ep = &g_end[(long)b * NCHUNK * NS + n];
    float* cp = &g_carry[(long)b * NCHUNK * NS + n];
    for (int c = 0; c < NCHUNK; c += 8) {
        float e[8];
        #pragma unroll
        for (int k = 0; k < 8; k++) e[k] = ep[(c + k) * NS];
        #pragma unroll
        for (int k = 0; k < 8; k++) {
            cp[(c + k) * NS] = carry;           // state entering chunk c+k
            carry = fmaf(al, carry, e[k]);      // fold chunk: A^L*carry + end
        }
    }
}

// ---------------------------------------------------------------------------
// K3: replay each chunk with its carry, emit y[t] = d[t] + sum_n w_n r_n[t].
// 4 warps per block, one warp per chunk; lane holds states n and n+32.
// ---------------------------------------------------------------------------
__global__ void __launch_bounds__(128) k3_scan(float* __restrict__ yout) {
    __shared__ float us[4][LCH];
    __shared__ float ys[4][LCH];
    const int lane = threadIdx.x & 31;
    const int w    = threadIdx.x >> 5;
    const int chunk = blockIdx.x * 4 + w;
    const long t0 = (long)chunk * LCH;

    #pragma unroll
    for (int e = lane; e < LCH; e += 32) us[w][e] = g_u[t0 + e];

    float a0 = g_A[lane],  a1 = g_A[lane + 32];
    float w0 = g_w[lane],  w1 = g_w[lane + 32];
    float r0 = g_carry[chunk * NS + lane];
    float r1 = g_carry[chunk * NS + lane + 32];
    __syncwarp();

    #pragma unroll 4
    for (int t = 0; t < LCH; t++) {
        float uv = us[w][t];
        r0 = fmaf(a0, r0, uv);
        r1 = fmaf(a1, r1, uv);
        float p = fmaf(w1, r1, w0 * r0);
        #pragma unroll
        for (int o = 16; o; o >>= 1) p += __shfl_xor_sync(0xffffffffu, p, o);
        if (lane == 0) ys[w][t] = p;
    }
    __syncwarp();

    #pragma unroll
    for (int e = lane; e < LCH; e += 32) yout[t0 + e] += ys[w][e];
}

// ---------------------------------------------------------------------------
extern "C" void kernel_launch(void* const* d_in, const int* in_sizes, int n_in,
                              void* d_out, int out_size) {
    const float* x    = (const float*)d_in[0];
    const float* W1   = (const float*)d_in[1];
    const float* b1   = (const float*)d_in[2];
    const float* W2   = (const float*)d_in[3];
    const float* b2   = (const float*)d_in[4];
    const float* Lraw = (const float*)d_in[5];
    const float* P    = (const float*)d_in[6];
    const float* Wu   = (const float*)d_in[7];
    const float* Cv   = (const float*)d_in[8];
    const float* Dv   = (const float*)d_in[9];
    const float* b_y  = (const float*)d_in[10];
    float* y = (float*)d_out;

    k0_params<<<1, 64>>>(W2, b2, Lraw, P, Wu, Cv, Dv, b_y);
    k1_mlp<<<TOTCHUNK, LCH>>>(x, W1, b1, y);
    k2_carry<<<BB, NS>>>();
    k3_scan<<<TOTCHUNK / 4, 128>>>(y);
}

// round 2
// speedup vs baseline: 1.3951x; 1.3951x over previous
#include <cuda_runtime.h>

// Problem constants (fixed shapes per reference)
#define BB 8
#define TT 32768
#define FIN 64
#define HID 32
#define FF 64
#define NS 64
#define LCH 256                 // chunk length (= rows per k1 block)
#define NCHUNK (TT / LCH)       // 128 chunks per batch
#define TOTCHUNK (BB * NCHUNK)  // 1024

// Derived parameters + scratch (device globals: no allocation allowed)
__device__ float g_A[NS];        // decay per state
__device__ float g_A128[NS];     // A^128
__device__ float g_AL[NS];       // A^LCH
__device__ float g_w[NS];        // C*P per state
__device__ float g_wU[HID];      // W2 @ Wu
__device__ float g_wD[HID];      // W2 @ D
__device__ float g_cU;           // b2 @ Wu
__device__ float g_cDy;          // b2 @ D + b_y
__device__ float g_u[BB * TT];           // scalar drive per timestep
__device__ float g_end[TOTCHUNK * NS];   // per-chunk local end states
__device__ float g_carry[TOTCHUNK * NS]; // carry-in state per chunk

// ---------------- packed f32x2 helpers ----------------
__device__ __forceinline__ unsigned long long pack2(float lo, float hi) {
    unsigned long long r;
    asm("mov.b64 %0, {%1,%2};" : "=l"(r) : "f"(lo), "f"(hi));
    return r;
}
__device__ __forceinline__ void unpack2(unsigned long long v, float& lo, float& hi) {
    asm("mov.b64 {%0,%1}, %2;" : "=f"(lo), "=f"(hi) : "l"(v));
}
__device__ __forceinline__ void fma2(unsigned long long& d,
                                     unsigned long long a, unsigned long long b) {
    asm("fma.rn.f32x2 %0, %1, %2, %0;" : "+l"(d) : "l"(a), "l"(b));
}

// ---------------------------------------------------------------------------
// K0: derive folded parameters. One block, 64 threads.
// ---------------------------------------------------------------------------
__global__ void k0_params(const float* __restrict__ W2, const float* __restrict__ b2,
                          const float* __restrict__ Lraw, const float* __restrict__ P,
                          const float* __restrict__ Wu, const float* __restrict__ Cv,
                          const float* __restrict__ Dv, const float* __restrict__ b_y) {
    int tid = threadIdx.x;
    if (tid < NS) {
        float lr = Lraw[tid];
        float sp = (lr > 20.f) ? lr : log1pf(expf(lr));   // softplus
        g_A[tid]    = expf(-sp);
        g_A128[tid] = expf(-sp * 128.f);
        g_AL[tid]   = expf(-sp * (float)LCH);
        g_w[tid]    = Cv[tid] * P[tid];
    }
    if (tid < HID) {
        float su = 0.f, sd = 0.f;
        for (int f = 0; f < FF; f++) {
            float w2 = W2[tid * FF + f];
            su = fmaf(w2, Wu[f], su);
            sd = fmaf(w2, Dv[f], sd);
        }
        g_wU[tid] = su;
        g_wD[tid] = sd;
    }
    if (tid == 0) {
        float cu = 0.f, cd = 0.f;
        for (int f = 0; f < FF; f++) {
            cu = fmaf(b2[f], Wu[f], cu);
            cd = fmaf(b2[f], Dv[f], cd);
        }
        g_cU  = cu;
        g_cDy = cd + b_y[0];
    }
}

// ---------------------------------------------------------------------------
// K1: MLP via register-tiled packed-f32x2 GEMM.
// Block = 1 chunk = 256 timesteps, 128 threads.
// Thread (cg = tid&3, rg = tid>>2) computes rows rg*8..rg*8+7, cols cg*8..cg*8+7.
// x staged in smem in two 32-wide k halves; W1 broadcast from smem.
// ---------------------------------------------------------------------------
__global__ void __launch_bounds__(128) k1_mlp(const float* __restrict__ x,
                                              const float* __restrict__ W1,
                                              const float* __restrict__ b1,
                                              float* __restrict__ yout) {
    __shared__ __align__(16) float xs[LCH][33];     // 33.8 KB, one k-half at a time
    __shared__ __align__(16) float W1s[FIN * HID];  // 8 KB
    __shared__ __align__(16) float us[LCH];
    __shared__ __align__(16) float ds[LCH];
    __shared__ float eh[2][NS];

    const int tid = threadIdx.x;
    const int cg  = tid & 3;            // column group (8 cols each)
    const int rg  = tid >> 2;           // row group (8 rows each)
    const int base = rg * 8;
    const int c0  = cg * 8;
    const int chunk = blockIdx.x;
    const long t0 = (long)chunk * LCH;

    // Stage full W1 (64x32) into smem
    for (int e = tid; e < FIN * HID; e += 128) W1s[e] = W1[e];

    // accumulators: 4 row-pairs x 8 cols, init to bias (dup in both halves)
    unsigned long long acc[4][8];
    #pragma unroll
    for (int c = 0; c < 8; c++) {
        float bv = b1[c0 + c];
        unsigned long long bp = pack2(bv, bv);
        #pragma unroll
        for (int rp = 0; rp < 4; rp++) acc[rp][c] = bp;
    }

    const float4* xg = (const float4*)(x + t0 * FIN);

    #pragma unroll
    for (int s = 0; s < 2; s++) {
        __syncthreads();   // protect xs from previous stage's readers
        // stage x[:, s*32 : s*32+32] -> xs[row][0..31]
        #pragma unroll
        for (int i = 0; i < 16; i++) {
            int e = tid + i * 128;          // 2048 float4 per stage
            int row = e >> 3;
            int q   = e & 7;
            float4 v = xg[row * 16 + s * 8 + q];
            float* dst = &xs[row][q * 4];
            dst[0] = v.x; dst[1] = v.y; dst[2] = v.z; dst[3] = v.w;
        }
        __syncthreads();

        #pragma unroll 4
        for (int kl = 0; kl < 32; kl++) {
            int kg = s * 32 + kl;
            // weights for this thread's 8 cols, duplicated into pairs
            const float* wrow = &W1s[kg * HID + c0];
            float4 wa = *(const float4*)(wrow);
            float4 wb = *(const float4*)(wrow + 4);
            unsigned long long wd[8];
            wd[0] = pack2(wa.x, wa.x); wd[1] = pack2(wa.y, wa.y);
            wd[2] = pack2(wa.z, wa.z); wd[3] = pack2(wa.w, wa.w);
            wd[4] = pack2(wb.x, wb.x); wd[5] = pack2(wb.y, wb.y);
            wd[6] = pack2(wb.z, wb.z); wd[7] = pack2(wb.w, wb.w);
            // x values for this thread's 8 rows, packed as row-pairs
            unsigned long long xp[4];
            #pragma unroll
            for (int rp = 0; rp < 4; rp++)
                xp[rp] = pack2(xs[base + 2 * rp][kl], xs[base + 2 * rp + 1][kl]);
            #pragma unroll
            for (int rp = 0; rp < 4; rp++) {
                #pragma unroll
                for (int c = 0; c < 8; c++) fma2(acc[rp][c], xp[rp], wd[c]);
            }
        }
    }

    // Epilogue: relu + project to (u, d); partial over this thread's 8 cols
    float uu[8], dd[8];
    #pragma unroll
    for (int j = 0; j < 8; j++) { uu[j] = 0.f; dd[j] = 0.f; }
    #pragma unroll
    for (int c = 0; c < 8; c++) {
        float wu = g_wU[c0 + c];
        float wdv = g_wD[c0 + c];
        #pragma unroll
        for (int rp = 0; rp < 4; rp++) {
            float h0, h1;
            unpack2(acc[rp][c], h0, h1);
            h0 = fmaxf(h0, 0.f); h1 = fmaxf(h1, 0.f);
            uu[2 * rp]     = fmaf(h0, wu, uu[2 * rp]);
            uu[2 * rp + 1] = fmaf(h1, wu, uu[2 * rp + 1]);
            dd[2 * rp]     = fmaf(h0, wdv, dd[2 * rp]);
            dd[2 * rp + 1] = fmaf(h1, wdv, dd[2 * rp + 1]);
        }
    }
    // reduce across the 4 column-groups (xor lanes 1,2)
    #pragma unroll
    for (int j = 0; j < 8; j++) {
        uu[j] += __shfl_xor_sync(0xffffffffu, uu[j], 1);
        uu[j] += __shfl_xor_sync(0xffffffffu, uu[j], 2);
        dd[j] += __shfl_xor_sync(0xffffffffu, dd[j], 1);
        dd[j] += __shfl_xor_sync(0xffffffffu, dd[j], 2);
    }
    if (cg == 0) {
        float cU = g_cU, cDy = g_cDy;
        #pragma unroll
        for (int j = 0; j < 8; j++) {
            us[base + j] = uu[j] + cU;
            ds[base + j] = dd[j] + cDy;
        }
    }
    __syncthreads();

    // cooperative stores of u and the feedthrough part of y
    if (tid < 64) {
        ((float4*)(g_u + t0))[tid]  = ((const float4*)us)[tid];
        ((float4*)(yout + t0))[tid] = ((const float4*)ds)[tid];
    }

    // local end-state: warps 0/1 each scan one 128-half from zero
    if (tid < 64) {
        int wh = tid >> 5;        // half 0 or 1
        int lane = tid & 31;
        float a0 = g_A[lane], a1 = g_A[lane + 32];
        float r0 = 0.f, r1 = 0.f;
        const float* up = &us[wh * 128];
        #pragma unroll 8
        for (int t = 0; t < 128; t++) {
            float uv = up[t];
            r0 = fmaf(a0, r0, uv);
            r1 = fmaf(a1, r1, uv);
        }
        eh[wh][lane]      = r0;
        eh[wh][lane + 32] = r1;
    }
    __syncthreads();
    if (tid < NS)
        g_end[chunk * NS + tid] = fmaf(g_A128[tid], eh[0][tid], eh[1][tid]);
}

// ---------------------------------------------------------------------------
// K2: scan carries across chunks, per batch. One block per batch, 64 threads
// (thread = state). Bulk-prefetch 64 end-states into registers per half.
// ---------------------------------------------------------------------------
__global__ void __launch_bounds__(NS) k2_carry() {
    const int b = blockIdx.x;
    const int n = threadIdx.x;
    const float al = g_AL[n];
    float carry = 0.f;
    const float* ep = &g_end[(long)b * NCHUNK * NS + n];
    float* cp = &g_carry[(long)b * NCHUNK * NS + n];
    #pragma unroll
    for (int h = 0; h < 2; h++) {
        float e[64];
        #pragma unroll
        for (int k = 0; k < 64; k++) e[k] = ep[(h * 64 + k) * NS];
        #pragma unroll
        for (int k = 0; k < 64; k++) {
            cp[(h * 64 + k) * NS] = carry;
            carry = fmaf(al, carry, e[k]);
        }
    }
}

// ---------------------------------------------------------------------------
// K3: replay each chunk with its carry; deferred cross-lane reduction via smem.
// 4 warps per block, one warp per 256-step chunk; lane holds states n, n+32.
// ---------------------------------------------------------------------------
__global__ void __launch_bounds__(128) k3_scan(float* __restrict__ yout) {
    __shared__ __align__(16) float us[4][LCH];
    __shared__ float ps[4][32][33];
    const int lane = threadIdx.x & 31;
    const int w    = threadIdx.x >> 5;
    const int chunk = blockIdx.x * 4 + w;
    const long t0 = (long)chunk * LCH;

    #pragma unroll
    for (int i = 0; i < 2; i++)
        ((float4*)us[w])[lane + 32 * i] = ((const float4*)(g_u + t0))[lane + 32 * i];

    float a0 = g_A[lane],  a1 = g_A[lane + 32];
    float w0 = g_w[lane],  w1 = g_w[lane + 32];
    float r0 = g_carry[chunk * NS + lane];
    float r1 = g_carry[chunk * NS + lane + 32];
    __syncwarp();

    #pragma unroll
    for (int tb = 0; tb < LCH / 32; tb++) {
        const float* up = &us[w][tb * 32];
        #pragma unroll
        for (int j = 0; j < 32; j++) {
            float uv = up[j];
            r0 = fmaf(a0, r0, uv);
            r1 = fmaf(a1, r1, uv);
            ps[w][j][lane] = fmaf(w1, r1, w0 * r0);
        }
        __syncwarp();
        // lane reduces timestep 'lane' of this tile (conflict-free: stride 33)
        float acc = 0.f;
        #pragma unroll
        for (int j2 = 0; j2 < 32; j2++) acc += ps[w][lane][j2];
        yout[t0 + tb * 32 + lane] += acc;
        __syncwarp();
    }
}

// ---------------------------------------------------------------------------
extern "C" void kernel_launch(void* const* d_in, const int* in_sizes, int n_in,
                              void* d_out, int out_size) {
    const float* x    = (const float*)d_in[0];
    const float* W1   = (const float*)d_in[1];
    const float* b1   = (const float*)d_in[2];
    const float* W2   = (const float*)d_in[3];
    const float* b2   = (const float*)d_in[4];
    const float* Lraw = (const float*)d_in[5];
    const float* P    = (const float*)d_in[6];
    const float* Wu   = (const float*)d_in[7];
    const float* Cv   = (const float*)d_in[8];
    const float* Dv   = (const float*)d_in[9];
    const float* b_y  = (const float*)d_in[10];
    float* y = (float*)d_out;

    k0_params<<<1, 64>>>(W2, b2, Lraw, P, Wu, Cv, Dv, b_y);
    k1_mlp<<<TOTCHUNK, 128>>>(x, W1, b1, y);
    k2_carry<<<BB, NS>>>();
    k3_scan<<<TOTCHUNK / 4, 128>>>(y);
}